// round 16
// baseline (speedup 1.0000x reference)
#include <cuda_runtime.h>
#include <math.h>

#define Bc   8
#define Sc   8192
#define Vc   64
#define Dc   256
#define DVc  32
#define DAGG 224     // D - DV
#define NTOK (Bc*Sc) // 65536
#define NBV  (Bc*Vc) // 512
#define CAP  Sc      // worst-case tokens per (b,v) segment
#define ABC_BLKS 32
#define PF_BLKS  32  // prefetch blocks appended to k_mid
#define SCAN_TOK 1024

// ---------------- scratch (device globals; no allocation) ----------------
__device__ float  g_A[DAGG], g_Bv[DAGG], g_C[DAGG];
__device__ float  g_part[ABC_BLKS][3][DAGG];
__device__ int    g_abc_ctr = 0;                           // self-resetting
__device__ float  g_pa[3][Dc], g_pb[3][Dc], g_pc[3][Dc];   // 0=q,1=k,2=v
__device__ float  g_Pvar[3][Vc][Dc];                       // var_emb @ W[0:32,:]
__device__ int    g_cnt[NBV];
__device__ float2 g_tok[NBV * CAP];                        // (val,tt) per segment
__device__ float  g_ctx[Bc][Dc];
__device__ float  g_sf[Bc][Dc];
__device__ float  g_p2[Bc][8];
__device__ int    g_ctr2[Bc];                              // zero-init, self-resetting
__device__ int    g_maskflags = 0;   // bit0: byte layout, bit1: float layout (OR idempotent)
__device__ float  g_sink;            // prefetch DCE guard

// ---------------- K1: parallel ABC collapse + mask detect + zero ----------------
__global__ void k_init(const float* __restrict__ me_w, const float* __restrict__ me_b,
                       const float* __restrict__ time_w, const float* __restrict__ time_b,
                       const float* __restrict__ agg_w, const float* __restrict__ agg_b,
                       const void* __restrict__ mask) {
    int blk = blockIdx.x;
    if (blk < ABC_BLKS) {
        int j = threadIdx.x;
        __shared__ bool isLast;
        if (j < DAGG) {
            float a = 0.f, b = 0.f, c = 0.f;
            int i0 = blk * 16;
            #pragma unroll
            for (int ii = 0; ii < 16; ii++) {
                int i = i0 + ii;
                if (i < 256) {
                    float w = agg_w[i * DAGG + j];
                    a += me_w[i] * w;  c += me_b[i] * w;
                } else {
                    int k = i - 256;
                    float w = agg_w[(256 + k) * DAGG + j];
                    b += time_w[k] * w;  c += time_b[k] * w;
                }
            }
            g_part[blk][0][j] = a;
            g_part[blk][1][j] = b;
            g_part[blk][2][j] = c;
        }
        __threadfence();
        __syncthreads();
        if (threadIdx.x == 0)
            isLast = (atomicAdd(&g_abc_ctr, 1) == ABC_BLKS - 1);
        __syncthreads();
        if (isLast) {
            if (j < DAGG) {
                float a = 0.f, b = 0.f, c = 0.f;
                #pragma unroll
                for (int r = 0; r < ABC_BLKS; r++) {
                    a += g_part[r][0][j];
                    b += g_part[r][1][j];
                    c += g_part[r][2][j];
                }
                g_A[j] = a; g_Bv[j] = b; g_C[j] = c + agg_b[j];
            }
            if (threadIdx.x == 0) g_abc_ctr = 0;
        }
    } else if (blk < ABC_BLKS + 8) {
        const unsigned int* w32 = (const unsigned int*)mask;
        int flags = 0;
        int base = (blk - ABC_BLKS) * 2048 + threadIdx.x;
        #pragma unroll
        for (int t = 0; t < 8; t++) {
            unsigned int w = w32[base + t * 256];
            if (w == 0x3f800000u) flags |= 2;
            else if (w > 1u)      flags |= 1;
        }
        __shared__ int sfl;
        if (threadIdx.x == 0) sfl = 0;
        __syncthreads();
        if (flags) atomicOr(&sfl, flags);
        __syncthreads();
        if (threadIdx.x == 0 && sfl) atomicOr(&g_maskflags, sfl);
    } else {
        int i = (blk - ABC_BLKS - 8) * 256 + threadIdx.x;   // 0..2047
        if (i < NBV) g_cnt[i] = 0;
        ((float*)g_ctx)[i] = 0.f;
    }
}

// ---------------- K2: projection constants || smem-bucketed token scan || L2 prefetch ----------------
__global__ void k_mid(const float* __restrict__ var_emb,
                      const float* __restrict__ wq, const float* __restrict__ bq,
                      const float* __restrict__ wk, const float* __restrict__ bk,
                      const float* __restrict__ wv, const float* __restrict__ bvv,
                      const int* __restrict__ fid, const void* __restrict__ mask,
                      const float* __restrict__ values, const float* __restrict__ times,
                      const float* __restrict__ wo, const float* __restrict__ cw1) {
    int blk = blockIdx.x;
    if (blk < 201) {
        int p = blk / 67, row = blk % 67;
        const float* W  = (p == 0) ? wq : (p == 1 ? wk : wv);
        const float* bb = (p == 0) ? bq : (p == 1 ? bk : bvv);
        int j = threadIdx.x;
        if (row < Vc) {
            const float* ve = &var_emb[row * DVc];
            float s = 0.f;
            #pragma unroll
            for (int i = 0; i < DVc; i++) s += ve[i] * W[i * Dc + j];
            g_Pvar[p][row][j] = s;
        } else {
            const float* src = (row == Vc) ? g_A : (row == Vc + 1 ? g_Bv : g_C);
            float s = 0.f;
            #pragma unroll 8
            for (int i = 0; i < DAGG; i++) s += src[i] * W[(DVc + i) * Dc + j];
            if      (row == Vc)     g_pa[p][j] = s;
            else if (row == Vc + 1) g_pb[p][j] = s;
            else                    g_pc[p][j] = s + bb[j];
        }
    } else if (blk < 265) {
        // ---- smem-bucketed scan: 1024 tokens (one batch) per block ----
        int c = blk - 201;                 // 0..63
        int b = c >> 3;                    // batch (8 chunks per batch)
        int tid = threadIdx.x;
        __shared__ float2 sdata[SCAN_TOK];
        __shared__ unsigned char svid[SCAN_TOK];
        __shared__ int scnt[Vc], soff[Vc], scur[Vc], sbase[Vc];
        __shared__ int sfl_sh;

        if (tid < Vc) { scnt[tid] = 0; scur[tid] = 0; }
        if (tid == 0) sfl_sh = g_maskflags;
        __syncthreads();
        // local layout detect: this block's byte-layout window (1024 bytes = 256 words)
        {
            unsigned w = ((const unsigned*)mask)[c * 256 + tid];
            if (w > 1u && w != 0x3f800000u) atomicOr(&sfl_sh, 1);
        }
        __syncthreads();
        int fl = sfl_sh;
        if (tid == 0 && fl) atomicOr(&g_maskflags, fl);

        int q = c * 256 + tid;             // global quad index
        bool ok[4];
        if (fl & 1) {
            unsigned u = ((const unsigned*)mask)[q];
            ok[0] = (u & 0xffu) != 0;      ok[1] = (u & 0xff00u) != 0;
            ok[2] = (u & 0xff0000u) != 0;  ok[3] = (u & 0xff000000u) != 0;
        } else {   // int32 / float32: identical nonzero bit test
            int4 m4 = ((const int4*)mask)[q];
            ok[0] = m4.x != 0; ok[1] = m4.y != 0; ok[2] = m4.z != 0; ok[3] = m4.w != 0;
        }
        float va[4], ta[4]; int fa[4];
        bool any = ok[0] | ok[1] | ok[2] | ok[3];
        if (any) {
            float4 vv = ((const float4*)values)[q];
            float4 tt = ((const float4*)times)[q];
            int4   ff = ((const int4*)fid)[q];
            va[0] = vv.x; va[1] = vv.y; va[2] = vv.z; va[3] = vv.w;
            ta[0] = tt.x; ta[1] = tt.y; ta[2] = tt.z; ta[3] = tt.w;
            fa[0] = ff.x; fa[1] = ff.y; fa[2] = ff.z; fa[3] = ff.w;
            #pragma unroll
            for (int u = 0; u < 4; u++)
                if (ok[u]) atomicAdd(&scnt[fa[u]], 1);
        }
        __syncthreads();
        if (tid == 0) {                    // exclusive scan over 64 counts
            int acc = 0;
            #pragma unroll
            for (int v = 0; v < Vc; v++) { soff[v] = acc; acc += scnt[v]; }
        }
        __syncthreads();
        if (any) {
            #pragma unroll
            for (int u = 0; u < 4; u++) {
                if (!ok[u]) continue;
                int v = fa[u];
                int slot = soff[v] + atomicAdd(&scur[v], 1);
                sdata[slot] = make_float2(va[u], ta[u]);
                svid[slot]  = (unsigned char)v;
            }
        }
        __syncthreads();
        if (tid < Vc && scnt[tid] > 0)
            sbase[tid] = atomicAdd(&g_cnt[b * Vc + tid], scnt[tid]);
        __syncthreads();
        int total = soff[Vc - 1] + scnt[Vc - 1];
        for (int idx = tid; idx < total; idx += 256) {
            int v = svid[idx];
            g_tok[(b * Vc + v) * CAP + sbase[v] + (idx - soff[v])] = sdata[idx];
        }
    } else {
        // ---- PF: warm L2 with wo and cw1 for k_f1/k_f2 ----
        int chunk = blk - 265;                  // 0..31
        const float4* s4 = (chunk < 16) ? (const float4*)wo : (const float4*)cw1;
        int base = (chunk & 15) * 1024 + threadIdx.x;   // 16KB chunks
        float acc = 0.f;
        #pragma unroll
        for (int i = 0; i < 4; i++) {
            float4 w = __ldcg(&s4[base + i * 256]);
            acc += w.x + w.y + w.z + w.w;
        }
        if (acc == 1.2345e-37f) g_sink = acc;   // DCE guard, never taken
    }
}

// ---------------- K3: segmented attention, affine-score form ----------------
__global__ void __launch_bounds__(256) k_attn(const int* __restrict__ fid,
                                              const float* __restrict__ values,
                                              const float* __restrict__ times) {
    int bv = blockIdx.x;
    int b = bv >> 6, v = bv & (Vc - 1);
    int tid = threadIdx.x;             // dim index d = h*32+lane
    int lane = tid & 31;
    int n = g_cnt[bv];

    float va = g_pa[2][tid], vb = g_pb[2][tid], vc = g_pc[2][tid];

    if (n == 0) {
        int t0 = b * Sc;
        float vx = g_Pvar[2][fid[t0]][tid] + values[t0] * va + times[t0] * vb + vc;
        atomicAdd(&g_ctx[b][tid], vx);
        return;
    }

    const float2* tok = &g_tok[bv * CAP];

    float s_v = 0.f, s_t = 0.f;
    for (int i = lane; i < n; i += 32) {
        float2 vt = tok[i];
        s_v += vt.x; s_t += vt.y;
    }
    #pragma unroll
    for (int o = 16; o > 0; o >>= 1) {
        s_v += __shfl_xor_sync(0xffffffffu, s_v, o);
        s_t += __shfl_xor_sync(0xffffffffu, s_t, o);
    }
    float inv_n = 1.0f / (float)n;
    float mv = s_v * inv_n, mt = s_t * inv_n;

    float q  = g_Pvar[0][v][tid] + mv * g_pa[0][tid] + mt * g_pb[0][tid] + g_pc[0][tid];
    float kk = g_Pvar[1][v][tid] + g_pc[1][tid];

    const float scale = 0.17677669529663687f;  // 1/sqrt(32)
    float al = q * kk, be = q * g_pa[1][tid], ga = q * g_pb[1][tid];
    #pragma unroll
    for (int o = 16; o > 0; o >>= 1) {
        al += __shfl_xor_sync(0xffffffffu, al, o);
        be += __shfl_xor_sync(0xffffffffu, be, o);
        ga += __shfl_xor_sync(0xffffffffu, ga, o);
    }
    al *= scale; be *= scale; ga *= scale;

    float m = -1e30f, l = 0.f, sv = 0.f, st = 0.f;
    for (int i = lane; i < n; i += 32) {
        float2 vt = tok[i];
        float s  = al + be * vt.x + ga * vt.y;
        float nm = fmaxf(m, s);
        float c  = __expf(m - nm);
        float e  = __expf(s - nm);
        l  = l * c + e;
        sv = sv * c + e * vt.x;
        st = st * c + e * vt.y;
        m = nm;
    }
    #pragma unroll
    for (int o = 16; o > 0; o >>= 1) {
        float m2  = __shfl_xor_sync(0xffffffffu, m, o);
        float l2  = __shfl_xor_sync(0xffffffffu, l, o);
        float sv2 = __shfl_xor_sync(0xffffffffu, sv, o);
        float st2 = __shfl_xor_sync(0xffffffffu, st, o);
        float nm = fmaxf(m, m2);
        float c1 = __expf(m - nm), c2 = __expf(m2 - nm);
        l  = l * c1 + l2 * c2;
        sv = sv * c1 + sv2 * c2;
        st = st * c1 + st2 * c2;
        m = nm;
    }
    float wv = sv / l, wt = st / l;
    float ctx = g_Pvar[2][v][tid] + vc + wv * va + wt * vb;
    atomicAdd(&g_ctx[b][tid], ctx);
}

// ---------------- K4a: GEMV1 in 32-col slices (64 blocks) ----------------
__global__ void __launch_bounds__(256) k_f1(const float* __restrict__ wo,
                                            const float* __restrict__ bo) {
    int b = blockIdx.x >> 3, slice = blockIdx.x & 7;
    int tid = threadIdx.x;
    int col = tid & 31, r = tid >> 5;       // 8 row-partitions x 32 cols
    int jg = slice * 32 + col;              // global output column
    __shared__ float sm[Dc];
    __shared__ float part[8][32];

    sm[tid] = g_ctx[b][tid] * (1.0f / Vc);
    __syncthreads();

    float acc = 0.f;
    #pragma unroll
    for (int ii = 0; ii < 32; ii++) {
        int i = r * 32 + ii;
        acc += sm[i] * wo[i * Dc + jg];
    }
    part[r][col] = acc;
    __syncthreads();
    if (r < 4) part[r][col] += part[r + 4][col];
    __syncthreads();
    if (r == 0)
        g_sf[b][jg] = part[0][col] + part[1][col] + part[2][col] + part[3][col] + bo[jg];
}

// ---------------- K4b: GEMV2 + relu + dot, slice partials, last-block finalize ----------------
__global__ void __launch_bounds__(256) k_f2(const float* __restrict__ cw1,
                                            const float* __restrict__ cb1,
                                            const float* __restrict__ cw2,
                                            const float* __restrict__ cb2,
                                            float* __restrict__ out) {
    int b = blockIdx.x >> 3, slice = blockIdx.x & 7;
    int tid = threadIdx.x;
    int col = tid & 31, r = tid >> 5;
    int jg = slice * 32 + col;
    __shared__ float sf[Dc];
    __shared__ float part[8][32];

    sf[tid] = g_sf[b][tid];
    __syncthreads();

    float acc = 0.f;
    #pragma unroll
    for (int ii = 0; ii < 32; ii++) {
        int i = r * 32 + ii;
        acc += sf[i] * cw1[i * Dc + jg];
    }
    part[r][col] = acc;
    __syncthreads();
    if (r < 4) part[r][col] += part[r + 4][col];
    __syncthreads();
    if (r == 0) {
        float h = part[0][col] + part[1][col] + part[2][col] + part[3][col] + cb1[jg];
        h = fmaxf(h, 0.f);
        float s = h * cw2[jg];
        #pragma unroll
        for (int o = 16; o > 0; o >>= 1) s += __shfl_xor_sync(0xffffffffu, s, o);
        if (col == 0) {
            g_p2[b][slice] = s;
            __threadfence();
            int done = atomicAdd(&g_ctr2[b], 1);
            if (done == 7) {
                float tot = 0.f;
                #pragma unroll
                for (int k = 0; k < 8; k++) tot += g_p2[b][k];
                out[b] = tot + cb2[0];
                g_ctr2[b] = 0;   // reset for next replay
            }
        }
    }
}

// ---------------- launch ----------------
extern "C" void kernel_launch(void* const* d_in, const int* in_sizes, int n_in,
                              void* d_out, int out_size) {
    const float* times   = (const float*)d_in[0];
    const int*   fid     = (const int*)  d_in[1];
    const float* values  = (const float*)d_in[2];
    const void*  mask    = (const void*) d_in[3];
    const float* me_w    = (const float*)d_in[4];
    const float* me_b    = (const float*)d_in[5];
    const float* var_emb = (const float*)d_in[6];
    const float* time_w  = (const float*)d_in[7];
    const float* time_b  = (const float*)d_in[8];
    const float* agg_w   = (const float*)d_in[9];
    const float* agg_b   = (const float*)d_in[10];
    const float* wq = (const float*)d_in[11]; const float* bq  = (const float*)d_in[12];
    const float* wk = (const float*)d_in[13]; const float* bk  = (const float*)d_in[14];
    const float* wv = (const float*)d_in[15]; const float* bvv = (const float*)d_in[16];
    const float* wo = (const float*)d_in[17]; const float* bo  = (const float*)d_in[18];
    const float* cw1 = (const float*)d_in[19]; const float* cb1 = (const float*)d_in[20];
    const float* cw2 = (const float*)d_in[21]; const float* cb2 = (const float*)d_in[22];
    float* out = (float*)d_out;

    k_init <<<ABC_BLKS + 8 + 8, 256>>>(me_w, me_b, time_w, time_b, agg_w, agg_b, mask);
    k_mid  <<<201 + 64 + PF_BLKS, 256>>>(var_emb, wq, bq, wk, bk, wv, bvv,
                                         fid, mask, values, times, wo, cw1);
    k_attn <<<NBV, 256>>>(fid, values, times);
    k_f1   <<<64, 256>>>(wo, bo);
    k_f2   <<<64, 256>>>(cw1, cb1, cw2, cb2, out);
}